// round 12
// baseline (speedup 1.0000x reference)
#include <cuda_runtime.h>
#include <math.h>

#define NPTS   16384
#define BATCH  2
#define HBEV   200
#define WBEV   176
#define CBEV   256
#define HW     (HBEV*WBEV)
#define KTOT   2048
#define NROWS  (BATCH*KTOT)
#define CMPN   8192
#define FULLM  0xffffffffu
#define NCONS  128

// ---------------- static device scratch ----------------
__device__ float4 g_pts[BATCH*NPTS];   // SoA points: x,y,z,intensity
__device__ float  g_kp[NROWS*3];       // keypoint coords
__device__ int    g_prog[6];           // per-(batch,band) published keypoint count

// ---------------- packed f32x2 + redux helpers ----------------
__device__ __forceinline__ unsigned long long pk2(float lo, float hi) {
    unsigned long long r; asm("mov.b64 %0, {%1, %2};" : "=l"(r) : "f"(lo), "f"(hi)); return r;
}
__device__ __forceinline__ void upk2(unsigned long long v, float& lo, float& hi) {
    asm("mov.b64 {%0, %1}, %2;" : "=f"(lo), "=f"(hi) : "l"(v));
}
__device__ __forceinline__ unsigned long long addx2(unsigned long long a, unsigned long long b) {
    unsigned long long r; asm("add.rn.f32x2 %0, %1, %2;" : "=l"(r) : "l"(a), "l"(b)); return r;
}
__device__ __forceinline__ unsigned long long mulx2(unsigned long long a, unsigned long long b) {
    unsigned long long r; asm("mul.rn.f32x2 %0, %1, %2;" : "=l"(r) : "l"(a), "l"(b)); return r;
}
__device__ __forceinline__ unsigned redux_maxu(unsigned v) {
    unsigned r; asm("redux.sync.max.u32 %0, %1, 0xffffffff;" : "=r"(r) : "r"(v)); return r;
}
__device__ __forceinline__ unsigned redux_minu(unsigned v) {
    unsigned r; asm("redux.sync.min.u32 %0, %1, 0xffffffff;" : "=r"(r) : "r"(v)); return r;
}

// ---------------- prep: SoA points + progress reset ----------------
__global__ void __launch_bounds__(512) prep_kernel(const float* __restrict__ pts) {
    int i = blockIdx.x*512 + threadIdx.x;
    if (i < BATCH*NPTS) {
        const float* p = pts + (size_t)i*5;
        g_pts[i] = make_float4(p[1], p[2], p[3], p[4]);
    }
    if (i < 6) g_prog[i] = 0;
}

// ==================================================================
// FPS body — verbatim R10 (measured 283.5us) + release publish /16 kp
// ==================================================================
template<int P>
__device__ __forceinline__ void fps_body(int run, int b, int K, int kpbase, int M,
                                         float* __restrict__ coords_out,
                                         unsigned (*sv)[16], unsigned (*si)[16]) {
    extern __shared__ float4 scmp[];
    int t = threadIdx.x;
    int lane = t & 31, warp = t >> 5;

    unsigned long long Xn[P], Yn[P], Zn[P];   // negated coords
    float D[2*P];
    #pragma unroll
    for (int p = 0; p < P; p++) {
        float4 a = scmp[(2*p)*512 + t];
        float4 c = scmp[(2*p+1)*512 + t];
        Xn[p] = pk2(-a.x, -c.x); Yn[p] = pk2(-a.y, -c.y); Zn[p] = pk2(-a.z, -c.z);
        D[2*p]   = ((2*p)*512 + t   < M) ? 1e10f : -1.0f;
        D[2*p+1] = ((2*p+1)*512 + t < M) ? 1e10f : -1.0f;
    }

    int sel = 0;   // first valid point = compacted index 0
    for (int k = 0; ; k++) {
        float4 w = scmp[sel];                // LDS broadcast
        if (t == 0) {
            int r = kpbase + k;
            g_kp[r*3+0] = w.x; g_kp[r*3+1] = w.y; g_kp[r*3+2] = w.z;
            coords_out[r*4+0] = (float)b;
            coords_out[r*4+1] = w.x; coords_out[r*4+2] = w.y; coords_out[r*4+3] = w.z;
            if ((k & 15) == 15) {            // publish progress (release orders kp stores)
                asm volatile("red.release.gpu.global.add.u32 [%0], %1;"
                             :: "l"(&g_prog[run]), "r"(16u) : "memory");
            }
        }
        if (k == K-1) break;

        unsigned long long wx = pk2(w.x, w.x);
        unsigned long long wy = pk2(w.y, w.y);
        unsigned long long wz = pk2(w.z, w.z);
        float bm[4] = {-1.f, -1.f, -1.f, -1.f};
        #pragma unroll
        for (int p = 0; p < P; p++) {
            unsigned long long dx = addx2(Xn[p], wx);   // (w-x): square == (x-w)^2 exactly
            unsigned long long dy = addx2(Yn[p], wy);
            unsigned long long dz = addx2(Zn[p], wz);
            unsigned long long d2 = addx2(addx2(mulx2(dx,dx), mulx2(dy,dy)), mulx2(dz,dz));
            float dl, dh; upk2(d2, dl, dh);
            float n0 = fminf(D[2*p],   dl); D[2*p]   = n0;
            float n1 = fminf(D[2*p+1], dh); D[2*p+1] = n1;
            bm[p & 3] = fmaxf(bm[p & 3], fmaxf(n0, n1));
        }
        float best = fmaxf(fmaxf(bm[0], bm[1]), fmaxf(bm[2], bm[3]));
        best = fmaxf(best, 0.0f);            // all-invalid thread: stays non-winner
        unsigned myidx = 0x7fffffffu;
        #pragma unroll
        for (int j = 2*P-1; j >= 0; j--)
            if (D[j] == best) myidx = (unsigned)(j*512 + t);   // smallest j wins

        unsigned u  = __float_as_uint(best); // d>=0 => bits order-isomorphic
        unsigned vm = redux_maxu(u);
        unsigned cand = (u == vm) ? myidx : 0x7fffffffu;
        unsigned im = redux_minu(cand);
        int par = k & 1;
        if (lane == 0) { sv[par][warp] = vm; si[par][warp] = im; }
        __syncthreads();
        unsigned v2 = sv[par][lane & 15];
        unsigned i2 = si[par][lane & 15];
        unsigned g  = redux_maxu(v2);
        unsigned c2 = (v2 == g) ? i2 : 0x7fffffffu;
        sel = (int)redux_minu(c2);
    }
}

// ==================================================================
// consumer: one 16-row group (bev + scan + MLP + GEMM), noinline to
// isolate registers from the FPS path.
// ==================================================================
__device__ __noinline__ void consumer_group(
        int g, const float* __restrict__ sf,
        const float* __restrict__ fw, const float* __restrict__ fbn,
        const float* sw0, const float* sw1,
        const float* sb0s, const float* sb0m, const float* sb0b,
        const float* sb1s, const float* sb1m, const float* sb1b,
        int* sidx /*[16][2][16]*/, int* scnt /*[16][2]*/, float* skp /*[48]*/,
        float* __restrict__ feats, float* __restrict__ fused) {
    extern __shared__ char dyn[];
    float2* sx = (float2*)dyn;                 // [1024]
    float2* sy = sx + 1024;
    float2* sz = sy + 1024;
    float*  sr = (float*)(sz + 1024);          // [16*288]
    float*  sp = sr + 16*288;                  // [4*16*128]

    int t = threadIdx.x;
    int lane = t & 31, w = t >> 5;

    int b = g >> 7;                 // 256 groups: 128 per batch
    int r7 = g & 127;
    int band = (r7 < 64) ? 0 : ((r7 < 96) ? 1 : 2);
    int k0 = (band == 0) ? r7*16 : ((band == 1) ? (r7-64)*16 : (r7-96)*16);
    int run = b*3 + band;
    int row0 = b*KTOT + ((band == 0) ? 0 : ((band == 1) ? 1024 : 1536)) + k0;
    const float4* Pp = g_pts + (size_t)b*NPTS;

    // ---- wait for the 16 keypoints of this group ----
    if (t == 0) {
        int need = k0 + 16;
        unsigned v;
        while (true) {
            asm volatile("ld.acquire.gpu.global.u32 %0, [%1];"
                         : "=r"(v) : "l"((unsigned*)&g_prog[run]) : "memory");
            if ((int)v >= need) break;
            __nanosleep(256);
        }
    }
    __syncthreads();
    if (t < 48) skp[t] = __ldcg(&g_kp[row0*3 + t]);   // L1-bypass (producer coherence)
    __syncthreads();

    // ---- phase A: BEV bilinear (512 thr = 2 x (8 rows x 256 ch)) ----
    {
        int c = t & 255, half = t >> 8;
        const float* ch = sf + ((size_t)b*CBEV + c)*HW;
        #pragma unroll 1
        for (int rr = 0; rr < 8; rr++) {
            int r = half*8 + rr;
            float kx = skp[r*3], ky = skp[r*3+1];
            float xi = ((kx - 0.0f)     / 0.05f) / 8.0f;
            float yi = ((ky - (-40.0f)) / 0.05f) / 8.0f;
            int x0 = (int)floorf(xi); int x1 = x0 + 1;
            int y0 = (int)floorf(yi); int y1 = y0 + 1;
            x0 = min(max(x0, 0), WBEV-1); x1 = min(max(x1, 0), WBEV-1);
            y0 = min(max(y0, 0), HBEV-1); y1 = min(max(y1, 0), HBEV-1);
            float x0f = (float)x0, x1f = (float)x1, y0f = (float)y0, y1f = (float)y1;
            float wa = (x1f - xi)*(y1f - yi);
            float wb = (x1f - xi)*(yi - y0f);
            float wc = (xi - x0f)*(y1f - yi);
            float wd = (xi - x0f)*(yi - y0f);
            float Ia = __ldg(ch + y0*WBEV + x0);
            float Ib = __ldg(ch + y1*WBEV + x0);
            float Ic = __ldg(ch + y0*WBEV + x1);
            float Id = __ldg(ch + y1*WBEV + x1);
            float val = Ia*wa + Ib*wb + Ic*wc + Id*wd;
            sr[r*288 + c] = val;
            feats[(size_t)(row0 + r)*288 + c] = val;
        }
    }

    // ---- phase B: ball-query scan, 1 row per warp (16 warps) ----
    {
        float kx = skp[w*3], ky = skp[w*3+1], kz = skp[w*3+2];
        unsigned long long nkx = pk2(-kx, -kx), nky = pk2(-ky, -ky), nkz = pk2(-kz, -kz);
        unsigned lt  = (1u << lane) - 1u;
        unsigned lte = lt | (1u << lane);
        int c1 = 0, c2 = 0;
        for (int base0 = 0; base0 < NPTS; base0 += 2048) {
            __syncthreads();
            #pragma unroll
            for (int i2 = 0; i2 < 2; i2++) {
                int j = t + i2*512;
                float4 p0 = Pp[base0 + 2*j];
                float4 p1 = Pp[base0 + 2*j + 1];
                sx[j] = make_float2(p0.x, p1.x);
                sy[j] = make_float2(p0.y, p1.y);
                sz[j] = make_float2(p0.z, p1.z);
            }
            __syncthreads();
            if (c1 >= 16 && c2 >= 16) continue;
            for (int o32 = 0; o32 < 1024; o32 += 32) {
                float2 vx = sx[o32 + lane], vy = sy[o32 + lane], vz = sz[o32 + lane];
                unsigned long long dx = addx2(pk2(vx.x, vx.y), nkx);
                unsigned long long dy = addx2(pk2(vy.x, vy.y), nky);
                unsigned long long dz = addx2(pk2(vz.x, vz.y), nkz);
                unsigned long long d2 = addx2(addx2(mulx2(dx,dx), mulx2(dy,dy)), mulx2(dz,dz));
                float da, db; upk2(d2, da, db);
                bool v2a = da < 4.0f, v2b = db < 4.0f;
                if (__ballot_sync(FULLM, v2a || v2b)) {
                    bool v1a = da < 1.0f, v1b = db < 1.0f;
                    unsigned m1e = __ballot_sync(FULLM, v1a);
                    unsigned m1o = __ballot_sync(FULLM, v1b);
                    unsigned m2e = __ballot_sync(FULLM, v2a);
                    unsigned m2o = __ballot_sync(FULLM, v2b);
                    int gi = base0 + 2*(o32 + lane);
                    if (c1 < 16 && (m1e | m1o)) {
                        int re = __popc(m1e & lt)  + __popc(m1o & lt);
                        int ro = __popc(m1e & lte) + __popc(m1o & lt);
                        if (v1a && c1 + re < 16) sidx[(w*2+0)*16 + c1+re] = gi;
                        if (v1b && c1 + ro < 16) sidx[(w*2+0)*16 + c1+ro] = gi + 1;
                        c1 = min(c1 + __popc(m1e) + __popc(m1o), 16);
                    }
                    if (c2 < 16 && (m2e | m2o)) {
                        int re = __popc(m2e & lt)  + __popc(m2o & lt);
                        int ro = __popc(m2e & lte) + __popc(m2o & lt);
                        if (v2a && c2 + re < 16) sidx[(w*2+1)*16 + c2+re] = gi;
                        if (v2b && c2 + ro < 16) sidx[(w*2+1)*16 + c2+ro] = gi + 1;
                        c2 = min(c2 + __popc(m2e) + __popc(m2o), 16);
                    }
                    if (c1 >= 16 && c2 >= 16) break;
                }
            }
        }
        __syncwarp();
        if (lane < 2) scnt[w*2 + lane] = lane ? c2 : c1;
    }
    __syncthreads();

    // ---- phase C: SA MLP + maxpool (32 groups of 16 threads) ----
    {
        int g16 = t >> 4, s = t & 15;
        int r = g16 >> 1, rI = g16 & 1;
        int row = row0 + r;
        float kx = skp[r*3], ky = skp[r*3+1], kz = skp[r*3+2];
        int cnt = scnt[r*2 + rI];
        float gx = 0.f, gy = 0.f, gz = 0.f, gi = 0.f;
        if (cnt > 0) {
            int id = sidx[(r*2+rI)*16 + ((s < cnt) ? s : 0)];
            float4 p = Pp[id];
            gx = p.x - kx; gy = p.y - ky; gz = p.z - kz; gi = p.w;
        }
        const float* W0  = sw0  + rI*64;
        const float* W1  = sw1  + rI*256;
        const float* B0s = sb0s + rI*16; const float* B0m = sb0m + rI*16; const float* B0b = sb0b + rI*16;
        const float* B1s = sb1s + rI*16; const float* B1m = sb1m + rI*16; const float* B1b = sb1b + rI*16;

        float h1[16];
        #pragma unroll
        for (int c = 0; c < 16; c++) {
            float a = gx*W0[c] + gy*W0[16+c] + gz*W0[32+c] + gi*W0[48+c];
            h1[c] = fmaxf((a - B0m[c])*B0s[c] + B0b[c], 0.0f);
        }
        float h2[16];
        #pragma unroll
        for (int c = 0; c < 16; c++) {
            float a = 0.f;
            #pragma unroll
            for (int k = 0; k < 16; k++) a += h1[k]*W1[k*16 + c];
            h2[c] = fmaxf((a - B1m[c])*B1s[c] + B1b[c], 0.0f);
        }
        #pragma unroll
        for (int off = 8; off; off >>= 1) {
            #pragma unroll
            for (int c = 0; c < 16; c++)
                h2[c] = fmaxf(h2[c], __shfl_xor_sync(FULLM, h2[c], off));
        }
        if (s == 0) {
            #pragma unroll
            for (int c = 0; c < 16; c++) {
                sr[r*288 + 256 + rI*16 + c] = h2[c];
                feats[(size_t)row*288 + 256 + rI*16 + c] = h2[c];
            }
        }
    }
    __syncthreads();

    // ---- phase D: 4-way split-k GEMM [16,288]@[288,128] + BN + ReLU ----
    {
        int q = t >> 7, outc = t & 127;     // quarter 0..3
        float acc[16];
        #pragma unroll
        for (int r = 0; r < 16; r++) acc[r] = 0.f;
        int kb = q*72;
        for (int k = kb; k < kb + 72; k++) {
            float wv = __ldg(fw + (size_t)k*128 + outc);
            #pragma unroll
            for (int r = 0; r < 16; r++) acc[r] += sr[r*288 + k] * wv;
        }
        #pragma unroll
        for (int r = 0; r < 16; r++) sp[(q*16 + r)*128 + outc] = acc[r];
    }
    __syncthreads();
    if (t < 128) {
        int outc = t;
        float gg = fbn[outc], be = fbn[128+outc], mm = fbn[256+outc], vv = fbn[384+outc];
        float sc = gg * (1.0f/sqrtf(vv + 1e-5f));
        #pragma unroll
        for (int r = 0; r < 16; r++) {
            float a = ((sp[(0*16+r)*128 + outc] + sp[(1*16+r)*128 + outc])
                     + (sp[(2*16+r)*128 + outc] + sp[(3*16+r)*128 + outc]));
            fused[(size_t)(row0 + r)*128 + outc] = fmaxf((a - mm)*sc + be, 0.f);
        }
    }
    __syncthreads();   // before next group reuses smem
}

// ==================================================================
// mega: blocks 0..5 FPS producers, blocks 6..133 consumers.
// grid 134 @ 1 block/SM (128KB smem) -> all co-resident, no deadlock.
// ==================================================================
__global__ void __launch_bounds__(512,1) mega_kernel(
        const float* __restrict__ pts,  const float* __restrict__ rng,
        const float* __restrict__ sf,
        const float* __restrict__ w0,   const float* __restrict__ bn0,
        const float* __restrict__ w1,   const float* __restrict__ bn1,
        const float* __restrict__ fw,   const float* __restrict__ fbn,
        float* __restrict__ coords_out, float* __restrict__ feats,
        float* __restrict__ fused) {
    extern __shared__ float4 scmp[];
    __shared__ unsigned sv[2][16], si[2][16];
    __shared__ int wsum[16];
    __shared__ int s_tot;
    // consumer statics
    __shared__ int   sidx[16*2*16];
    __shared__ int   scnt[16*2];
    __shared__ float skp[48];
    __shared__ float sw0[128], sw1[512];
    __shared__ float sb0s[32], sb0m[32], sb0b[32];
    __shared__ float sb1s[32], sb1m[32], sb1b[32];

    int t = threadIdx.x;
    int lane = t & 31, warp = t >> 5;

    if (blockIdx.x < 6) {
        // ================= FPS producer (verbatim R10) =================
        int run = blockIdx.x, b = run/3, band = run - b*3;

        const float4* R4 = (const float4*)(rng + (size_t)b*NPTS) + t*8;
        unsigned bits = 0; int cnt = 0;
        #pragma unroll
        for (int q = 0; q < 8; q++) {
            float4 r4 = R4[q];
            float rr[4] = {r4.x, r4.y, r4.z, r4.w};
            #pragma unroll
            for (int u = 0; u < 4; u++) {
                float r = rr[u];
                bool sh = (r > 0.0f) && (r < 25.0f);
                bool lg = (r > 45.0f);
                bool v = (band == 0) ? sh : ((band == 2) ? lg : (!lg && !sh));
                if (v) { bits |= (1u << (q*4+u)); cnt++; }
            }
        }
        int inc = cnt;
        #pragma unroll
        for (int off = 1; off < 32; off <<= 1) {
            int o = __shfl_up_sync(FULLM, inc, off);
            if (lane >= off) inc += o;
        }
        if (lane == 31) wsum[warp] = inc;
        __syncthreads();
        if (warp == 0 && lane < 16) {
            int v = wsum[lane];
            #pragma unroll
            for (int off = 1; off < 16; off <<= 1) {
                int o = __shfl_up_sync(0xffffu, v, off);
                if (lane >= off) v += o;
            }
            wsum[lane] = v;
            if (lane == 15) s_tot = v;
        }
        __syncthreads();
        int off0 = inc - cnt + (warp ? wsum[warp-1] : 0);
        const float* PP = pts + (size_t)b*NPTS*5;
        for (int u = 0; u < 32; u++) {
            if ((bits >> u) & 1u) {
                if (off0 < CMPN) {
                    const float* p = PP + (size_t)(t*32 + u)*5;
                    scmp[off0] = make_float4(p[1], p[2], p[3], p[4]);
                }
                off0++;
            }
        }
        int M = min(s_tot, CMPN);
        for (int i = M + t; i < CMPN; i += 512)
            scmp[i] = make_float4(1e15f, 1e15f, 1e15f, 0.f);
        __syncthreads();

        int K = (band == 0) ? 1024 : 512;
        int kpbase = b*KTOT + (band==0 ? 0 : (band==1 ? 1024 : 1536));
        int P = min(8, (M + 1023) >> 10);
        switch (P) {
            case 1:  fps_body<1>(run, b, K, kpbase, M, coords_out, sv, si); break;
            case 2:  fps_body<2>(run, b, K, kpbase, M, coords_out, sv, si); break;
            case 3:  fps_body<3>(run, b, K, kpbase, M, coords_out, sv, si); break;
            case 4:  fps_body<4>(run, b, K, kpbase, M, coords_out, sv, si); break;
            case 5:  fps_body<5>(run, b, K, kpbase, M, coords_out, sv, si); break;
            case 6:  fps_body<6>(run, b, K, kpbase, M, coords_out, sv, si); break;
            case 7:  fps_body<7>(run, b, K, kpbase, M, coords_out, sv, si); break;
            default: fps_body<8>(run, b, K, kpbase, M, coords_out, sv, si); break;
        }
        return;
    }

    // ================= consumers =================
    int cb = (int)blockIdx.x - 6;

    if (t < 128) sw0[t] = w0[t];
    sw1[t] = w1[t];
    if (t < 384) { /* nothing */ }
    for (int i = t + 512; i < 512 + 0; i += 512) {}
    if (t >= 128 && t < 512) { }     // (kept minimal; sw1 full load below)
    // full sw1 load (512 floats by 512 threads done above only for t<512 once)
    // -- already covered: sw1[t] = w1[t] for all t in [0,512)

    if (t < 32) {
        int br = t >> 4, c = t & 15;
        float g = bn0[br*64 + c], be = bn0[br*64+16+c], m = bn0[br*64+32+c], v = bn0[br*64+48+c];
        sb0s[t] = g * (1.0f/sqrtf(v + 1e-5f)); sb0m[t] = m; sb0b[t] = be;
        g = bn1[br*64 + c]; be = bn1[br*64+16+c]; m = bn1[br*64+32+c]; v = bn1[br*64+48+c];
        sb1s[t] = g * (1.0f/sqrtf(v + 1e-5f)); sb1m[t] = m; sb1b[t] = be;
    }
    __syncthreads();

    // two groups per block, paired early+late so each block has <=1 late group
    consumer_group(cb, sf, fw, fbn, sw0, sw1, sb0s, sb0m, sb0b, sb1s, sb1m, sb1b,
                   sidx, scnt, skp, feats, fused);
    consumer_group(255 - cb, sf, fw, fbn, sw0, sw1, sb0s, sb0m, sb0b, sb1s, sb1m, sb1b,
                   sidx, scnt, skp, feats, fused);
}

// ---------------- launch ----------------
extern "C" void kernel_launch(void* const* d_in, const int* in_sizes, int n_in,
                              void* d_out, int out_size) {
    const float* points = (const float*)d_in[0];
    const float* rng    = (const float*)d_in[1];
    const float* sf     = (const float*)d_in[2];
    const float* sa_w0  = (const float*)d_in[3];
    const float* sa_bn0 = (const float*)d_in[4];
    const float* sa_w1  = (const float*)d_in[5];
    const float* sa_bn1 = (const float*)d_in[6];
    const float* fw     = (const float*)d_in[7];
    const float* fbn    = (const float*)d_in[8];
    float* out = (float*)d_out;

    float* fused  = out;                                          // [4096,128]
    float* feats  = out + (size_t)NROWS*128;                      // [4096,288]
    float* coords = out + (size_t)NROWS*128 + (size_t)NROWS*288;  // [4096,4]

    const int MEGA_SMEM = CMPN * (int)sizeof(float4);   // 128 KB dynamic
    cudaFuncSetAttribute(mega_kernel, cudaFuncAttributeMaxDynamicSharedMemorySize, MEGA_SMEM);

    prep_kernel<<<(BATCH*NPTS + 511)/512, 512>>>(points);
    mega_kernel<<<6 + NCONS, 512, MEGA_SMEM>>>(points, rng, sf,
                                               sa_w0, sa_bn0, sa_w1, sa_bn1,
                                               fw, fbn, coords, feats, fused);
}

// round 13
// speedup vs baseline: 1.1451x; 1.1451x over previous
#include <cuda_runtime.h>
#include <math.h>

#define NPTS   16384
#define BATCH  2
#define HBEV   200
#define WBEV   176
#define CBEV   256
#define HW     (HBEV*WBEV)
#define KTOT   2048
#define NROWS  (BATCH*KTOT)
#define CMPN   8192
#define FULLM  0xffffffffu
#define CX     36
#define CY     40
#define NCELL  (CX*CY)
#define CAP    224

// ---------------- static device scratch ----------------
__device__ float4 g_pts[BATCH*NPTS];        // SoA points
__device__ float  g_kp[NROWS*3];            // keypoint coords
__device__ float4 g_binpts[BATCH*NPTS];     // grid-binned points
__device__ int    g_binidx[BATCH*NPTS];     // binned -> original index
__device__ int    g_cellstart[BATCH][NCELL+1];

// ---------------- packed f32x2 + redux helpers ----------------
__device__ __forceinline__ unsigned long long pk2(float lo, float hi) {
    unsigned long long r; asm("mov.b64 %0, {%1, %2};" : "=l"(r) : "f"(lo), "f"(hi)); return r;
}
__device__ __forceinline__ void upk2(unsigned long long v, float& lo, float& hi) {
    asm("mov.b64 {%0, %1}, %2;" : "=f"(lo), "=f"(hi) : "l"(v));
}
__device__ __forceinline__ unsigned long long addx2(unsigned long long a, unsigned long long b) {
    unsigned long long r; asm("add.rn.f32x2 %0, %1, %2;" : "=l"(r) : "l"(a), "l"(b)); return r;
}
__device__ __forceinline__ unsigned long long mulx2(unsigned long long a, unsigned long long b) {
    unsigned long long r; asm("mul.rn.f32x2 %0, %1, %2;" : "=l"(r) : "l"(a), "l"(b)); return r;
}
__device__ __forceinline__ unsigned redux_maxu(unsigned v) {
    unsigned r; asm("redux.sync.max.u32 %0, %1, 0xffffffff;" : "=r"(r) : "r"(v)); return r;
}
__device__ __forceinline__ unsigned redux_minu(unsigned v) {
    unsigned r; asm("redux.sync.min.u32 %0, %1, 0xffffffff;" : "=r"(r) : "r"(v)); return r;
}
__device__ __forceinline__ int cell_of(float x, float y) {
    int cx = min(CX-1, max(0, (int)(x * 0.5f)));
    int cy = min(CY-1, max(0, (int)((y + 40.0f) * 0.5f)));
    return cy*CX + cx;
}

// ==================================================================
// prep: blocks 0..63 SoA build; blocks 64,65 grid binning (1 per batch)
// ==================================================================
__global__ void __launch_bounds__(512) prep_kernel(const float* __restrict__ pts) {
    __shared__ int cellcnt[NCELL];
    __shared__ int coff[1536];
    __shared__ int wtot[16];
    int t = threadIdx.x;
    int lane = t & 31, warp = t >> 5;

    if (blockIdx.x < 64) {
        int i = blockIdx.x*512 + t;
        const float* p = pts + (size_t)i*5;
        g_pts[i] = make_float4(p[1], p[2], p[3], p[4]);
        return;
    }

    // ---- binning for batch b ----
    int b = (int)blockIdx.x - 64;
    const float* PB = pts + (size_t)b*NPTS*5;
    for (int i = t; i < NCELL; i += 512) cellcnt[i] = 0;
    __syncthreads();
    for (int i = t; i < NPTS; i += 512) {
        const float* p = PB + (size_t)i*5;
        atomicAdd(&cellcnt[cell_of(p[1], p[2])], 1);
    }
    __syncthreads();
    // exclusive scan of NCELL counts (3 per thread)
    int base = t*3;
    int a0 = (base   < NCELL) ? cellcnt[base]   : 0;
    int a1 = (base+1 < NCELL) ? cellcnt[base+1] : 0;
    int a2 = (base+2 < NCELL) ? cellcnt[base+2] : 0;
    int s = a0 + a1 + a2;
    int inc = s;
    #pragma unroll
    for (int off = 1; off < 32; off <<= 1) {
        int o = __shfl_up_sync(FULLM, inc, off);
        if (lane >= off) inc += o;
    }
    if (lane == 31) wtot[warp] = inc;
    __syncthreads();
    if (warp == 0 && lane < 16) {
        int v = wtot[lane];
        #pragma unroll
        for (int off = 1; off < 16; off <<= 1) {
            int o = __shfl_up_sync(0xffffu, v, off);
            if (lane >= off) v += o;
        }
        wtot[lane] = v;
    }
    __syncthreads();
    int exc = inc - s + (warp ? wtot[warp-1] : 0);
    if (base   < NCELL) { coff[base]   = exc;        g_cellstart[b][base]   = exc; }
    if (base+1 < NCELL) { coff[base+1] = exc+a0;     g_cellstart[b][base+1] = exc+a0; }
    if (base+2 < NCELL) { coff[base+2] = exc+a0+a1;  g_cellstart[b][base+2] = exc+a0+a1; }
    if (t == 0) g_cellstart[b][NCELL] = NPTS;
    __syncthreads();
    // scatter
    for (int i = t; i < NPTS; i += 512) {
        const float* p = PB + (size_t)i*5;
        float x = p[1], y = p[2];
        int pos = atomicAdd(&coff[cell_of(x, y)], 1);
        g_binpts[b*NPTS + pos] = make_float4(x, y, p[3], p[4]);
        g_binidx[b*NPTS + pos] = i;
    }
}

// ==================================================================
// FPS — verbatim R5 (measured-best): 256 threads, redux tail.
// ==================================================================
template<int P>
__device__ __forceinline__ void fps_body(int b, int K, int kpbase, int M,
                                         float* __restrict__ coords_out,
                                         unsigned (*sv)[8], unsigned (*si)[8]) {
    extern __shared__ float4 scmp[];
    int t = threadIdx.x;
    int lane = t & 31, warp = t >> 5;

    unsigned long long Xn[P], Yn[P], Zn[P];
    float D[2*P];
    #pragma unroll
    for (int p = 0; p < P; p++) {
        float4 a = scmp[(2*p)*256 + t];
        float4 c = scmp[(2*p+1)*256 + t];
        Xn[p] = pk2(-a.x, -c.x); Yn[p] = pk2(-a.y, -c.y); Zn[p] = pk2(-a.z, -c.z);
        D[2*p]   = ((2*p)*256 + t   < M) ? 1e10f : -1.0f;
        D[2*p+1] = ((2*p+1)*256 + t < M) ? 1e10f : -1.0f;
    }

    int sel = 0;
    for (int k = 0; ; k++) {
        float4 w = scmp[sel];
        if (t == 0) {
            int r = kpbase + k;
            g_kp[r*3+0] = w.x; g_kp[r*3+1] = w.y; g_kp[r*3+2] = w.z;
            coords_out[r*4+0] = (float)b;
            coords_out[r*4+1] = w.x; coords_out[r*4+2] = w.y; coords_out[r*4+3] = w.z;
        }
        if (k == K-1) break;

        unsigned long long wx = pk2(w.x, w.x);
        unsigned long long wy = pk2(w.y, w.y);
        unsigned long long wz = pk2(w.z, w.z);
        float bm[4] = {-1.f, -1.f, -1.f, -1.f};
        #pragma unroll
        for (int p = 0; p < P; p++) {
            unsigned long long dx = addx2(Xn[p], wx);
            unsigned long long dy = addx2(Yn[p], wy);
            unsigned long long dz = addx2(Zn[p], wz);
            unsigned long long d2 = addx2(addx2(mulx2(dx,dx), mulx2(dy,dy)), mulx2(dz,dz));
            float dl, dh; upk2(d2, dl, dh);
            float n0 = fminf(D[2*p],   dl); D[2*p]   = n0;
            float n1 = fminf(D[2*p+1], dh); D[2*p+1] = n1;
            bm[p & 3] = fmaxf(bm[p & 3], fmaxf(n0, n1));
        }
        float best = fmaxf(fmaxf(bm[0], bm[1]), fmaxf(bm[2], bm[3]));
        best = fmaxf(best, 0.0f);
        unsigned myidx = 0x7fffffffu;
        #pragma unroll
        for (int j = 2*P-1; j >= 0; j--)
            if (D[j] == best) myidx = (unsigned)(j*256 + t);

        unsigned u  = __float_as_uint(best);
        unsigned vm = redux_maxu(u);
        unsigned cand = (u == vm) ? myidx : 0x7fffffffu;
        unsigned im = redux_minu(cand);
        int par = k & 1;
        if (lane == 0) { sv[par][warp] = vm; si[par][warp] = im; }
        __syncthreads();
        unsigned v2 = sv[par][lane & 7];
        unsigned i2 = si[par][lane & 7];
        unsigned g  = redux_maxu(v2);
        unsigned c2 = (v2 == g) ? i2 : 0x7fffffffu;
        sel = (int)redux_minu(c2);
    }
}

__global__ void __launch_bounds__(256,1) fps_kernel(const float* __restrict__ pts,
                                                    const float* __restrict__ rng,
                                                    float* __restrict__ coords_out) {
    extern __shared__ float4 scmp[];
    __shared__ unsigned sv[2][8];
    __shared__ unsigned si[2][8];
    __shared__ int wsum[8];
    __shared__ int s_tot;

    int run = blockIdx.x, b = run/3, band = run - b*3;
    int t = threadIdx.x;
    int lane = t & 31, warp = t >> 5;

    const float4* R4 = (const float4*)(rng + (size_t)b*NPTS) + t*16;
    unsigned long long bits = 0; int cnt = 0;
    #pragma unroll
    for (int q = 0; q < 16; q++) {
        float4 r4 = R4[q];
        float rr[4] = {r4.x, r4.y, r4.z, r4.w};
        #pragma unroll
        for (int u = 0; u < 4; u++) {
            float r = rr[u];
            bool sh = (r > 0.0f) && (r < 25.0f);
            bool lg = (r > 45.0f);
            bool v = (band == 0) ? sh : ((band == 2) ? lg : (!lg && !sh));
            if (v) { bits |= (1ull << (q*4+u)); cnt++; }
        }
    }
    int inc = cnt;
    #pragma unroll
    for (int off = 1; off < 32; off <<= 1) {
        int o = __shfl_up_sync(FULLM, inc, off);
        if (lane >= off) inc += o;
    }
    if (lane == 31) wsum[warp] = inc;
    __syncthreads();
    if (warp == 0 && lane < 8) {
        int v = wsum[lane];
        #pragma unroll
        for (int off = 1; off < 8; off <<= 1) {
            int o = __shfl_up_sync(0xffu, v, off);
            if (lane >= off) v += o;
        }
        wsum[lane] = v;
        if (lane == 7) s_tot = v;
    }
    __syncthreads();
    int off0 = inc - cnt + (warp ? wsum[warp-1] : 0);
    const float* PP = pts + (size_t)b*NPTS*5;
    for (int u = 0; u < 64; u++) {
        if ((bits >> u) & 1ull) {
            if (off0 < CMPN) {
                const float* p = PP + (size_t)(t*64 + u)*5;
                scmp[off0] = make_float4(p[1], p[2], p[3], p[4]);
            }
            off0++;
        }
    }
    int M = min(s_tot, CMPN);
    for (int i = M + t; i < CMPN; i += 256)
        scmp[i] = make_float4(1e15f, 1e15f, 1e15f, 0.f);
    __syncthreads();

    int K = (band == 0) ? 1024 : 512;
    int kpbase = b*KTOT + (band==0 ? 0 : (band==1 ? 1024 : 1536));
    int P = min(16, ((M + 1023) >> 10) * 2);
    switch (P) {
        case 2:  fps_body<2>(b, K, kpbase, M, coords_out, sv, si); break;
        case 4:  fps_body<4>(b, K, kpbase, M, coords_out, sv, si); break;
        case 6:  fps_body<6>(b, K, kpbase, M, coords_out, sv, si); break;
        case 8:  fps_body<8>(b, K, kpbase, M, coords_out, sv, si); break;
        case 10: fps_body<10>(b, K, kpbase, M, coords_out, sv, si); break;
        case 12: fps_body<12>(b, K, kpbase, M, coords_out, sv, si); break;
        case 14: fps_body<14>(b, K, kpbase, M, coords_out, sv, si); break;
        default: fps_body<16>(b, K, kpbase, M, coords_out, sv, si); break;
    }
}

// ==================================================================
// backend: bev + cell-based ball-query + MLP + split-k GEMM.
// 512 blocks x 256 thr, 8 rows per block. Selection by min-index
// extraction — valid because maxpool output is order/dup invariant.
// ==================================================================
__global__ void __launch_bounds__(256) backend_kernel(
        const float* __restrict__ sf,
        const float* __restrict__ w0, const float* __restrict__ bn0,
        const float* __restrict__ w1, const float* __restrict__ bn1,
        const float* __restrict__ fw, const float* __restrict__ fbn,
        float* __restrict__ feats, float* __restrict__ out) {
    __shared__ unsigned slist[8*CAP];
    __shared__ int   ssel[8][2][16];
    __shared__ int   scnt[8][2];
    __shared__ float sr[8*288];
    __shared__ float sp[2][8][128];
    __shared__ float sw0[128], sw1[512];
    __shared__ float sb0s[32], sb0m[32], sb0b[32];
    __shared__ float sb1s[32], sb1m[32], sb1b[32];
    __shared__ float skp[24];

    int t = threadIdx.x;
    int lane = t & 31, w = t >> 5;
    int row0 = blockIdx.x*8;
    int b = row0 >> 11;
    const float4* Pp = g_pts + (size_t)b*NPTS;

    if (t < 128) sw0[t] = w0[t];
    sw1[t] = w1[t]; sw1[t + 256] = w1[t + 256];
    if (t < 32) {
        int br = t >> 4, c = t & 15;
        float g = bn0[br*64 + c], be = bn0[br*64+16+c], m = bn0[br*64+32+c], v = bn0[br*64+48+c];
        sb0s[t] = g * (1.0f/sqrtf(v + 1e-5f)); sb0m[t] = m; sb0b[t] = be;
        g = bn1[br*64 + c]; be = bn1[br*64+16+c]; m = bn1[br*64+32+c]; v = bn1[br*64+48+c];
        sb1s[t] = g * (1.0f/sqrtf(v + 1e-5f)); sb1m[t] = m; sb1b[t] = be;
    }
    if (t < 24) skp[t] = g_kp[row0*3 + t];
    __syncthreads();

    // ---- phase A: BEV bilinear (1 channel/thread, 8 rows) ----
    {
        const float* ch = sf + ((size_t)b*CBEV + t)*HW;
        #pragma unroll 1
        for (int r = 0; r < 8; r++) {
            float kx = skp[r*3], ky = skp[r*3+1];
            float xi = ((kx - 0.0f)     / 0.05f) / 8.0f;
            float yi = ((ky - (-40.0f)) / 0.05f) / 8.0f;
            int x0 = (int)floorf(xi); int x1 = x0 + 1;
            int y0 = (int)floorf(yi); int y1 = y0 + 1;
            x0 = min(max(x0, 0), WBEV-1); x1 = min(max(x1, 0), WBEV-1);
            y0 = min(max(y0, 0), HBEV-1); y1 = min(max(y1, 0), HBEV-1);
            float x0f = (float)x0, x1f = (float)x1, y0f = (float)y0, y1f = (float)y1;
            float wa = (x1f - xi)*(y1f - yi);
            float wb = (x1f - xi)*(yi - y0f);
            float wc = (xi - x0f)*(y1f - yi);
            float wd = (xi - x0f)*(yi - y0f);
            float Ia = __ldg(ch + y0*WBEV + x0);
            float Ib = __ldg(ch + y1*WBEV + x0);
            float Ic = __ldg(ch + y0*WBEV + x1);
            float Id = __ldg(ch + y1*WBEV + x1);
            float val = Ia*wa + Ib*wb + Ic*wc + Id*wd;
            sr[r*288 + t] = val;
            feats[(size_t)(row0 + r)*288 + t] = val;
        }
    }

    // ---- phase B: cell-based ball query, 1 row per warp ----
    {
        float kx = skp[w*3], ky = skp[w*3+1], kz = skp[w*3+2];
        int kcx = min(CX-1, max(0, (int)(kx * 0.5f)));
        int kcy = min(CY-1, max(0, (int)((ky + 40.0f) * 0.5f)));
        unsigned lt = (1u << lane) - 1u;
        unsigned* L = slist + w*CAP;
        int cnt2 = 0;
        const float4* BP = g_binpts + (size_t)b*NPTS;
        const int*    BI = g_binidx + (size_t)b*NPTS;
        for (int cy = max(0, kcy-1); cy <= min(CY-1, kcy+1); cy++) {
            for (int cx = max(0, kcx-1); cx <= min(CX-1, kcx+1); cx++) {
                int c = cy*CX + cx;
                int s0 = g_cellstart[b][c], s1 = g_cellstart[b][c+1];
                for (int base = s0; base < s1; base += 32) {
                    int i = base + lane;
                    bool in = i < s1;
                    float4 p = in ? BP[i] : make_float4(1e9f, 1e9f, 1e9f, 0.f);
                    // exact rn chain, matches reference discretely
                    float dx = __fadd_rn(p.x, -kx);
                    float dy = __fadd_rn(p.y, -ky);
                    float dz = __fadd_rn(p.z, -kz);
                    float d2 = __fadd_rn(__fadd_rn(__fmul_rn(dx,dx), __fmul_rn(dy,dy)), __fmul_rn(dz,dz));
                    bool v2 = in && (d2 < 4.0f);
                    bool v1 = v2 && (d2 < 1.0f);
                    unsigned m2 = __ballot_sync(FULLM, v2);
                    if (m2) {
                        int rank = __popc(m2 & lt);
                        if (v2 && cnt2 + rank < CAP)
                            L[cnt2 + rank] = (unsigned)BI[i] | (v1 ? 0x10000u : 0u);
                        cnt2 = min(cnt2 + __popc(m2), CAP);
                    }
                }
            }
        }
        // load candidates into registers
        unsigned e[7];
        #pragma unroll
        for (int j = 0; j < 7; j++) {
            int pos = lane + j*32;
            e[j] = (pos < cnt2) ? L[pos] : 0xFFFFFFFFu;
        }
        // select 16 smallest original indices (r=2)
        {
            unsigned wv[7];
            #pragma unroll
            for (int j = 0; j < 7; j++) wv[j] = (e[j] == 0xFFFFFFFFu) ? 0xFFFFu : (e[j] & 0xFFFFu);
            int csel = 0;
            for (int r = 0; r < 16; r++) {
                unsigned lm = 0xFFFFu;
                #pragma unroll
                for (int j = 0; j < 7; j++) lm = min(lm, wv[j]);
                unsigned g = redux_minu(lm);
                if (g == 0xFFFFu) break;
                if (lane == r) ssel[w][1][r] = (int)g;
                csel++;
                #pragma unroll
                for (int j = 0; j < 7; j++) if (wv[j] == g) wv[j] = 0xFFFFu;
            }
            if (lane == 0) scnt[w][1] = csel;
        }
        // select 16 smallest original indices (r=1: flagged entries)
        {
            unsigned wv[7];
            #pragma unroll
            for (int j = 0; j < 7; j++)
                wv[j] = (e[j] != 0xFFFFFFFFu && (e[j] & 0x10000u)) ? (e[j] & 0xFFFFu) : 0xFFFFu;
            int csel = 0;
            for (int r = 0; r < 16; r++) {
                unsigned lm = 0xFFFFu;
                #pragma unroll
                for (int j = 0; j < 7; j++) lm = min(lm, wv[j]);
                unsigned g = redux_minu(lm);
                if (g == 0xFFFFu) break;
                if (lane == r) ssel[w][0][r] = (int)g;
                csel++;
                #pragma unroll
                for (int j = 0; j < 7; j++) if (wv[j] == g) wv[j] = 0xFFFFu;
            }
            if (lane == 0) scnt[w][0] = csel;
        }
    }
    __syncthreads();

    // ---- phase C: SA MLP + maxpool (16 groups of 16 threads) ----
    {
        int g16 = t >> 4, s = t & 15;
        int r = g16 >> 1, rI = g16 & 1;
        int row = row0 + r;
        float kx = skp[r*3], ky = skp[r*3+1], kz = skp[r*3+2];
        int cnt = scnt[r][rI];
        float gx = 0.f, gy = 0.f, gz = 0.f, gi = 0.f;
        if (cnt > 0) {
            int id = ssel[r][rI][(s < cnt) ? s : 0];
            float4 p = Pp[id];
            gx = p.x - kx; gy = p.y - ky; gz = p.z - kz; gi = p.w;
        }
        const float* W0  = sw0  + rI*64;
        const float* W1  = sw1  + rI*256;
        const float* B0s = sb0s + rI*16; const float* B0m = sb0m + rI*16; const float* B0b = sb0b + rI*16;
        const float* B1s = sb1s + rI*16; const float* B1m = sb1m + rI*16; const float* B1b = sb1b + rI*16;

        float h1[16];
        #pragma unroll
        for (int c = 0; c < 16; c++) {
            float a = gx*W0[c] + gy*W0[16+c] + gz*W0[32+c] + gi*W0[48+c];
            h1[c] = fmaxf((a - B0m[c])*B0s[c] + B0b[c], 0.0f);
        }
        float h2[16];
        #pragma unroll
        for (int c = 0; c < 16; c++) {
            float a = 0.f;
            #pragma unroll
            for (int k = 0; k < 16; k++) a += h1[k]*W1[k*16 + c];
            h2[c] = fmaxf((a - B1m[c])*B1s[c] + B1b[c], 0.0f);
        }
        #pragma unroll
        for (int off = 8; off; off >>= 1) {
            #pragma unroll
            for (int c = 0; c < 16; c++)
                h2[c] = fmaxf(h2[c], __shfl_xor_sync(FULLM, h2[c], off));
        }
        if (s == 0) {
            #pragma unroll
            for (int c = 0; c < 16; c++) {
                sr[r*288 + 256 + rI*16 + c] = h2[c];
                feats[(size_t)row*288 + 256 + rI*16 + c] = h2[c];
            }
        }
    }
    __syncthreads();

    // ---- phase D: split-k GEMM [8,288]@[288,128] + BN + ReLU ----
    {
        int half = t >> 7, outc = t & 127;
        float acc[8] = {0.f,0.f,0.f,0.f,0.f,0.f,0.f,0.f};
        int kb = half*144;
        for (int k = kb; k < kb + 144; k++) {
            float wv = __ldg(fw + (size_t)k*128 + outc);
            #pragma unroll
            for (int r = 0; r < 8; r++) acc[r] += sr[r*288 + k] * wv;
        }
        #pragma unroll
        for (int r = 0; r < 8; r++) sp[half][r][outc] = acc[r];
    }
    __syncthreads();
    if (t < 128) {
        int outc = t;
        float g = fbn[outc], be = fbn[128+outc], m = fbn[256+outc], v = fbn[384+outc];
        float sc = g * (1.0f/sqrtf(v + 1e-5f));
        #pragma unroll
        for (int r = 0; r < 8; r++) {
            float a = sp[0][r][outc] + sp[1][r][outc];
            out[(size_t)(row0 + r)*128 + outc] = fmaxf((a - m)*sc + be, 0.f);
        }
    }
}

// ---------------- launch ----------------
extern "C" void kernel_launch(void* const* d_in, const int* in_sizes, int n_in,
                              void* d_out, int out_size) {
    const float* points = (const float*)d_in[0];
    const float* rng    = (const float*)d_in[1];
    const float* sf     = (const float*)d_in[2];
    const float* sa_w0  = (const float*)d_in[3];
    const float* sa_bn0 = (const float*)d_in[4];
    const float* sa_w1  = (const float*)d_in[5];
    const float* sa_bn1 = (const float*)d_in[6];
    const float* fw     = (const float*)d_in[7];
    const float* fbn    = (const float*)d_in[8];
    float* out = (float*)d_out;

    float* fused  = out;                                          // [4096,128]
    float* feats  = out + (size_t)NROWS*128;                      // [4096,288]
    float* coords = out + (size_t)NROWS*128 + (size_t)NROWS*288;  // [4096,4]

    const int FPS_SMEM = CMPN * (int)sizeof(float4);   // 128 KB
    cudaFuncSetAttribute(fps_kernel, cudaFuncAttributeMaxDynamicSharedMemorySize, FPS_SMEM);

    prep_kernel<<<66, 512>>>(points);
    fps_kernel<<<6, 256, FPS_SMEM>>>(points, rng, coords);
    backend_kernel<<<NROWS/8, 256>>>(sf, sa_w0, sa_bn0, sa_w1, sa_bn1, fw, fbn, feats, fused);
}

// round 14
// speedup vs baseline: 1.2413x; 1.0841x over previous
#include <cuda_runtime.h>
#include <math.h>

#define NPTS   16384
#define BATCH  2
#define HBEV   200
#define WBEV   176
#define CBEV   256
#define HW     (HBEV*WBEV)
#define KTOT   2048
#define NROWS  (BATCH*KTOT)
#define CMPN   8192
#define FULLM  0xffffffffu
#define CX     36
#define CY     40
#define NCELL  (CX*CY)
#define CAP    224

// ---------------- static device scratch ----------------
__device__ float4 g_pts[BATCH*NPTS];        // SoA points
__device__ float  g_kp[NROWS*3];            // keypoint coords
__device__ float4 g_binpts[BATCH*NPTS];     // grid-binned points
__device__ int    g_binidx[BATCH*NPTS];     // binned -> original index
__device__ int    g_cellstart[BATCH][NCELL+1];

// ---------------- packed f32x2 + redux helpers ----------------
__device__ __forceinline__ unsigned long long pk2(float lo, float hi) {
    unsigned long long r; asm("mov.b64 %0, {%1, %2};" : "=l"(r) : "f"(lo), "f"(hi)); return r;
}
__device__ __forceinline__ void upk2(unsigned long long v, float& lo, float& hi) {
    asm("mov.b64 {%0, %1}, %2;" : "=f"(lo), "=f"(hi) : "l"(v));
}
__device__ __forceinline__ unsigned long long addx2(unsigned long long a, unsigned long long b) {
    unsigned long long r; asm("add.rn.f32x2 %0, %1, %2;" : "=l"(r) : "l"(a), "l"(b)); return r;
}
__device__ __forceinline__ unsigned long long mulx2(unsigned long long a, unsigned long long b) {
    unsigned long long r; asm("mul.rn.f32x2 %0, %1, %2;" : "=l"(r) : "l"(a), "l"(b)); return r;
}
__device__ __forceinline__ unsigned redux_maxu(unsigned v) {
    unsigned r; asm("redux.sync.max.u32 %0, %1, 0xffffffff;" : "=r"(r) : "r"(v)); return r;
}
__device__ __forceinline__ unsigned redux_minu(unsigned v) {
    unsigned r; asm("redux.sync.min.u32 %0, %1, 0xffffffff;" : "=r"(r) : "r"(v)); return r;
}
__device__ __forceinline__ int cell_of(float x, float y) {
    int cx = min(CX-1, max(0, (int)(x * 0.5f)));
    int cy = min(CY-1, max(0, (int)((y + 40.0f) * 0.5f)));
    return cy*CX + cx;
}

// ==================================================================
// FPS body — verbatim R5/R13 (measured-best): 256 threads, redux tail.
// ==================================================================
template<int P>
__device__ __forceinline__ void fps_body(int b, int K, int kpbase, int M,
                                         float* __restrict__ coords_out,
                                         unsigned (*sv)[8], unsigned (*si)[8]) {
    extern __shared__ float4 scmp[];
    int t = threadIdx.x;
    int lane = t & 31, warp = t >> 5;

    unsigned long long Xn[P], Yn[P], Zn[P];
    float D[2*P];
    #pragma unroll
    for (int p = 0; p < P; p++) {
        float4 a = scmp[(2*p)*256 + t];
        float4 c = scmp[(2*p+1)*256 + t];
        Xn[p] = pk2(-a.x, -c.x); Yn[p] = pk2(-a.y, -c.y); Zn[p] = pk2(-a.z, -c.z);
        D[2*p]   = ((2*p)*256 + t   < M) ? 1e10f : -1.0f;
        D[2*p+1] = ((2*p+1)*256 + t < M) ? 1e10f : -1.0f;
    }

    int sel = 0;
    for (int k = 0; ; k++) {
        float4 w = scmp[sel];
        if (t == 0) {
            int r = kpbase + k;
            g_kp[r*3+0] = w.x; g_kp[r*3+1] = w.y; g_kp[r*3+2] = w.z;
            coords_out[r*4+0] = (float)b;
            coords_out[r*4+1] = w.x; coords_out[r*4+2] = w.y; coords_out[r*4+3] = w.z;
        }
        if (k == K-1) break;

        unsigned long long wx = pk2(w.x, w.x);
        unsigned long long wy = pk2(w.y, w.y);
        unsigned long long wz = pk2(w.z, w.z);
        float bm[4] = {-1.f, -1.f, -1.f, -1.f};
        #pragma unroll
        for (int p = 0; p < P; p++) {
            unsigned long long dx = addx2(Xn[p], wx);
            unsigned long long dy = addx2(Yn[p], wy);
            unsigned long long dz = addx2(Zn[p], wz);
            unsigned long long d2 = addx2(addx2(mulx2(dx,dx), mulx2(dy,dy)), mulx2(dz,dz));
            float dl, dh; upk2(d2, dl, dh);
            float n0 = fminf(D[2*p],   dl); D[2*p]   = n0;
            float n1 = fminf(D[2*p+1], dh); D[2*p+1] = n1;
            bm[p & 3] = fmaxf(bm[p & 3], fmaxf(n0, n1));
        }
        float best = fmaxf(fmaxf(bm[0], bm[1]), fmaxf(bm[2], bm[3]));
        best = fmaxf(best, 0.0f);
        unsigned myidx = 0x7fffffffu;
        #pragma unroll
        for (int j = 2*P-1; j >= 0; j--)
            if (D[j] == best) myidx = (unsigned)(j*256 + t);

        unsigned u  = __float_as_uint(best);
        unsigned vm = redux_maxu(u);
        unsigned cand = (u == vm) ? myidx : 0x7fffffffu;
        unsigned im = redux_minu(cand);
        int par = k & 1;
        if (lane == 0) { sv[par][warp] = vm; si[par][warp] = im; }
        __syncthreads();
        unsigned v2 = sv[par][lane & 7];
        unsigned i2 = si[par][lane & 7];
        unsigned g  = redux_maxu(v2);
        unsigned c2 = (v2 == g) ? i2 : 0x7fffffffu;
        sel = (int)redux_minu(c2);
    }
}

// ==================================================================
// fps+prep: blocks 0..5 FPS; 6..69 SoA build; 70..71 grid binning.
// All groups independent (no cross-block waits); binning reuses the
// 128KB dynamic smem for its histograms (no static growth on FPS path).
// ==================================================================
__global__ void __launch_bounds__(256,1) fps_kernel(const float* __restrict__ pts,
                                                    const float* __restrict__ rng,
                                                    float* __restrict__ coords_out) {
    extern __shared__ float4 scmp[];
    __shared__ unsigned sv[2][8];
    __shared__ unsigned si[2][8];
    __shared__ int wsum[8];
    __shared__ int s_tot;

    int t = threadIdx.x;
    int lane = t & 31, warp = t >> 5;

    if (blockIdx.x >= 70) {
        // ---- grid binning for batch b (smem histograms alias scmp) ----
        int* cellcnt = (int*)scmp;            // [NCELL]
        int* coff    = cellcnt + NCELL;       // [NCELL]
        int b = (int)blockIdx.x - 70;
        const float* PB = pts + (size_t)b*NPTS*5;
        for (int i = t; i < NCELL; i += 256) cellcnt[i] = 0;
        __syncthreads();
        for (int i = t; i < NPTS; i += 256) {
            const float* p = PB + (size_t)i*5;
            atomicAdd(&cellcnt[cell_of(p[1], p[2])], 1);
        }
        __syncthreads();
        // exclusive scan of NCELL counts (6 per thread)
        int base = t*6;
        int a[6]; int s = 0;
        #pragma unroll
        for (int j = 0; j < 6; j++) {
            a[j] = (base + j < NCELL) ? cellcnt[base + j] : 0;
            s += a[j];
        }
        int inc = s;
        #pragma unroll
        for (int off = 1; off < 32; off <<= 1) {
            int o = __shfl_up_sync(FULLM, inc, off);
            if (lane >= off) inc += o;
        }
        if (lane == 31) wsum[warp] = inc;
        __syncthreads();
        if (warp == 0 && lane < 8) {
            int v = wsum[lane];
            #pragma unroll
            for (int off = 1; off < 8; off <<= 1) {
                int o = __shfl_up_sync(0xffu, v, off);
                if (lane >= off) v += o;
            }
            wsum[lane] = v;
        }
        __syncthreads();
        int exc = inc - s + (warp ? wsum[warp-1] : 0);
        #pragma unroll
        for (int j = 0; j < 6; j++) {
            if (base + j < NCELL) {
                coff[base + j] = exc;
                g_cellstart[b][base + j] = exc;
            }
            exc += a[j];
        }
        if (t == 0) g_cellstart[b][NCELL] = NPTS;
        __syncthreads();
        // scatter
        for (int i = t; i < NPTS; i += 256) {
            const float* p = PB + (size_t)i*5;
            float x = p[1], y = p[2];
            int pos = atomicAdd(&coff[cell_of(x, y)], 1);
            g_binpts[b*NPTS + pos] = make_float4(x, y, p[3], p[4]);
            g_binidx[b*NPTS + pos] = i;
        }
        return;
    }

    if (blockIdx.x >= 6) {
        // ---- SoA build on otherwise-idle SMs (64 blocks) ----
        for (int i = ((int)blockIdx.x - 6)*256 + t; i < BATCH*NPTS; i += 64*256) {
            const float* p = pts + (size_t)i*5;
            g_pts[i] = make_float4(p[1], p[2], p[3], p[4]);
        }
        return;
    }

    // ================= FPS (verbatim R13) =================
    int run = blockIdx.x, b = run/3, band = run - b*3;

    const float4* R4 = (const float4*)(rng + (size_t)b*NPTS) + t*16;
    unsigned long long bits = 0; int cnt = 0;
    #pragma unroll
    for (int q = 0; q < 16; q++) {
        float4 r4 = R4[q];
        float rr[4] = {r4.x, r4.y, r4.z, r4.w};
        #pragma unroll
        for (int u = 0; u < 4; u++) {
            float r = rr[u];
            bool sh = (r > 0.0f) && (r < 25.0f);
            bool lg = (r > 45.0f);
            bool v = (band == 0) ? sh : ((band == 2) ? lg : (!lg && !sh));
            if (v) { bits |= (1ull << (q*4+u)); cnt++; }
        }
    }
    int inc = cnt;
    #pragma unroll
    for (int off = 1; off < 32; off <<= 1) {
        int o = __shfl_up_sync(FULLM, inc, off);
        if (lane >= off) inc += o;
    }
    if (lane == 31) wsum[warp] = inc;
    __syncthreads();
    if (warp == 0 && lane < 8) {
        int v = wsum[lane];
        #pragma unroll
        for (int off = 1; off < 8; off <<= 1) {
            int o = __shfl_up_sync(0xffu, v, off);
            if (lane >= off) v += o;
        }
        wsum[lane] = v;
        if (lane == 7) s_tot = v;
    }
    __syncthreads();
    int off0 = inc - cnt + (warp ? wsum[warp-1] : 0);
    const float* PP = pts + (size_t)b*NPTS*5;
    for (int u = 0; u < 64; u++) {
        if ((bits >> u) & 1ull) {
            if (off0 < CMPN) {
                const float* p = PP + (size_t)(t*64 + u)*5;
                scmp[off0] = make_float4(p[1], p[2], p[3], p[4]);
            }
            off0++;
        }
    }
    int M = min(s_tot, CMPN);
    for (int i = M + t; i < CMPN; i += 256)
        scmp[i] = make_float4(1e15f, 1e15f, 1e15f, 0.f);
    __syncthreads();

    int K = (band == 0) ? 1024 : 512;
    int kpbase = b*KTOT + (band==0 ? 0 : (band==1 ? 1024 : 1536));
    int P = min(16, ((M + 1023) >> 10) * 2);
    switch (P) {
        case 2:  fps_body<2>(b, K, kpbase, M, coords_out, sv, si); break;
        case 4:  fps_body<4>(b, K, kpbase, M, coords_out, sv, si); break;
        case 6:  fps_body<6>(b, K, kpbase, M, coords_out, sv, si); break;
        case 8:  fps_body<8>(b, K, kpbase, M, coords_out, sv, si); break;
        case 10: fps_body<10>(b, K, kpbase, M, coords_out, sv, si); break;
        case 12: fps_body<12>(b, K, kpbase, M, coords_out, sv, si); break;
        case 14: fps_body<14>(b, K, kpbase, M, coords_out, sv, si); break;
        default: fps_body<16>(b, K, kpbase, M, coords_out, sv, si); break;
    }
}

// ==================================================================
// backend — verbatim R13: bev + cell ball-query + MLP + split-k GEMM.
// ==================================================================
__global__ void __launch_bounds__(256) backend_kernel(
        const float* __restrict__ sf,
        const float* __restrict__ w0, const float* __restrict__ bn0,
        const float* __restrict__ w1, const float* __restrict__ bn1,
        const float* __restrict__ fw, const float* __restrict__ fbn,
        float* __restrict__ feats, float* __restrict__ out) {
    __shared__ unsigned slist[8*CAP];
    __shared__ int   ssel[8][2][16];
    __shared__ int   scnt[8][2];
    __shared__ float sr[8*288];
    __shared__ float sp[2][8][128];
    __shared__ float sw0[128], sw1[512];
    __shared__ float sb0s[32], sb0m[32], sb0b[32];
    __shared__ float sb1s[32], sb1m[32], sb1b[32];
    __shared__ float skp[24];

    int t = threadIdx.x;
    int lane = t & 31, w = t >> 5;
    int row0 = blockIdx.x*8;
    int b = row0 >> 11;
    const float4* Pp = g_pts + (size_t)b*NPTS;

    if (t < 128) sw0[t] = w0[t];
    sw1[t] = w1[t]; sw1[t + 256] = w1[t + 256];
    if (t < 32) {
        int br = t >> 4, c = t & 15;
        float g = bn0[br*64 + c], be = bn0[br*64+16+c], m = bn0[br*64+32+c], v = bn0[br*64+48+c];
        sb0s[t] = g * (1.0f/sqrtf(v + 1e-5f)); sb0m[t] = m; sb0b[t] = be;
        g = bn1[br*64 + c]; be = bn1[br*64+16+c]; m = bn1[br*64+32+c]; v = bn1[br*64+48+c];
        sb1s[t] = g * (1.0f/sqrtf(v + 1e-5f)); sb1m[t] = m; sb1b[t] = be;
    }
    if (t < 24) skp[t] = g_kp[row0*3 + t];
    __syncthreads();

    // ---- phase A: BEV bilinear (1 channel/thread, 8 rows) ----
    {
        const float* ch = sf + ((size_t)b*CBEV + t)*HW;
        #pragma unroll 1
        for (int r = 0; r < 8; r++) {
            float kx = skp[r*3], ky = skp[r*3+1];
            float xi = ((kx - 0.0f)     / 0.05f) / 8.0f;
            float yi = ((ky - (-40.0f)) / 0.05f) / 8.0f;
            int x0 = (int)floorf(xi); int x1 = x0 + 1;
            int y0 = (int)floorf(yi); int y1 = y0 + 1;
            x0 = min(max(x0, 0), WBEV-1); x1 = min(max(x1, 0), WBEV-1);
            y0 = min(max(y0, 0), HBEV-1); y1 = min(max(y1, 0), HBEV-1);
            float x0f = (float)x0, x1f = (float)x1, y0f = (float)y0, y1f = (float)y1;
            float wa = (x1f - xi)*(y1f - yi);
            float wb = (x1f - xi)*(yi - y0f);
            float wc = (xi - x0f)*(y1f - yi);
            float wd = (xi - x0f)*(yi - y0f);
            float Ia = __ldg(ch + y0*WBEV + x0);
            float Ib = __ldg(ch + y1*WBEV + x0);
            float Ic = __ldg(ch + y0*WBEV + x1);
            float Id = __ldg(ch + y1*WBEV + x1);
            float val = Ia*wa + Ib*wb + Ic*wc + Id*wd;
            sr[r*288 + t] = val;
            feats[(size_t)(row0 + r)*288 + t] = val;
        }
    }

    // ---- phase B: cell-based ball query, 1 row per warp ----
    {
        float kx = skp[w*3], ky = skp[w*3+1], kz = skp[w*3+2];
        int kcx = min(CX-1, max(0, (int)(kx * 0.5f)));
        int kcy = min(CY-1, max(0, (int)((ky + 40.0f) * 0.5f)));
        unsigned lt = (1u << lane) - 1u;
        unsigned* L = slist + w*CAP;
        int cnt2 = 0;
        const float4* BP = g_binpts + (size_t)b*NPTS;
        const int*    BI = g_binidx + (size_t)b*NPTS;
        for (int cy = max(0, kcy-1); cy <= min(CY-1, kcy+1); cy++) {
            for (int cx = max(0, kcx-1); cx <= min(CX-1, kcx+1); cx++) {
                int c = cy*CX + cx;
                int s0 = g_cellstart[b][c], s1 = g_cellstart[b][c+1];
                for (int base = s0; base < s1; base += 32) {
                    int i = base + lane;
                    bool in = i < s1;
                    float4 p = in ? BP[i] : make_float4(1e9f, 1e9f, 1e9f, 0.f);
                    float dx = __fadd_rn(p.x, -kx);
                    float dy = __fadd_rn(p.y, -ky);
                    float dz = __fadd_rn(p.z, -kz);
                    float d2 = __fadd_rn(__fadd_rn(__fmul_rn(dx,dx), __fmul_rn(dy,dy)), __fmul_rn(dz,dz));
                    bool v2 = in && (d2 < 4.0f);
                    bool v1 = v2 && (d2 < 1.0f);
                    unsigned m2 = __ballot_sync(FULLM, v2);
                    if (m2) {
                        int rank = __popc(m2 & lt);
                        if (v2 && cnt2 + rank < CAP)
                            L[cnt2 + rank] = (unsigned)BI[i] | (v1 ? 0x10000u : 0u);
                        cnt2 = min(cnt2 + __popc(m2), CAP);
                    }
                }
            }
        }
        unsigned e[7];
        #pragma unroll
        for (int j = 0; j < 7; j++) {
            int pos = lane + j*32;
            e[j] = (pos < cnt2) ? L[pos] : 0xFFFFFFFFu;
        }
        {
            unsigned wv[7];
            #pragma unroll
            for (int j = 0; j < 7; j++) wv[j] = (e[j] == 0xFFFFFFFFu) ? 0xFFFFu : (e[j] & 0xFFFFu);
            int csel = 0;
            for (int r = 0; r < 16; r++) {
                unsigned lm = 0xFFFFu;
                #pragma unroll
                for (int j = 0; j < 7; j++) lm = min(lm, wv[j]);
                unsigned g = redux_minu(lm);
                if (g == 0xFFFFu) break;
                if (lane == r) ssel[w][1][r] = (int)g;
                csel++;
                #pragma unroll
                for (int j = 0; j < 7; j++) if (wv[j] == g) wv[j] = 0xFFFFu;
            }
            if (lane == 0) scnt[w][1] = csel;
        }
        {
            unsigned wv[7];
            #pragma unroll
            for (int j = 0; j < 7; j++)
                wv[j] = (e[j] != 0xFFFFFFFFu && (e[j] & 0x10000u)) ? (e[j] & 0xFFFFu) : 0xFFFFu;
            int csel = 0;
            for (int r = 0; r < 16; r++) {
                unsigned lm = 0xFFFFu;
                #pragma unroll
                for (int j = 0; j < 7; j++) lm = min(lm, wv[j]);
                unsigned g = redux_minu(lm);
                if (g == 0xFFFFu) break;
                if (lane == r) ssel[w][0][r] = (int)g;
                csel++;
                #pragma unroll
                for (int j = 0; j < 7; j++) if (wv[j] == g) wv[j] = 0xFFFFu;
            }
            if (lane == 0) scnt[w][0] = csel;
        }
    }
    __syncthreads();

    // ---- phase C: SA MLP + maxpool (16 groups of 16 threads) ----
    {
        int g16 = t >> 4, s = t & 15;
        int r = g16 >> 1, rI = g16 & 1;
        int row = row0 + r;
        float kx = skp[r*3], ky = skp[r*3+1], kz = skp[r*3+2];
        int cnt = scnt[r][rI];
        float gx = 0.f, gy = 0.f, gz = 0.f, gi = 0.f;
        if (cnt > 0) {
            int id = ssel[r][rI][(s < cnt) ? s : 0];
            float4 p = Pp[id];
            gx = p.x - kx; gy = p.y - ky; gz = p.z - kz; gi = p.w;
        }
        const float* W0  = sw0  + rI*64;
        const float* W1  = sw1  + rI*256;
        const float* B0s = sb0s + rI*16; const float* B0m = sb0m + rI*16; const float* B0b = sb0b + rI*16;
        const float* B1s = sb1s + rI*16; const float* B1m = sb1m + rI*16; const float* B1b = sb1b + rI*16;

        float h1[16];
        #pragma unroll
        for (int c = 0; c < 16; c++) {
            float a = gx*W0[c] + gy*W0[16+c] + gz*W0[32+c] + gi*W0[48+c];
            h1[c] = fmaxf((a - B0m[c])*B0s[c] + B0b[c], 0.0f);
        }
        float h2[16];
        #pragma unroll
        for (int c = 0; c < 16; c++) {
            float a = 0.f;
            #pragma unroll
            for (int k = 0; k < 16; k++) a += h1[k]*W1[k*16 + c];
            h2[c] = fmaxf((a - B1m[c])*B1s[c] + B1b[c], 0.0f);
        }
        #pragma unroll
        for (int off = 8; off; off >>= 1) {
            #pragma unroll
            for (int c = 0; c < 16; c++)
                h2[c] = fmaxf(h2[c], __shfl_xor_sync(FULLM, h2[c], off));
        }
        if (s == 0) {
            #pragma unroll
            for (int c = 0; c < 16; c++) {
                sr[r*288 + 256 + rI*16 + c] = h2[c];
                feats[(size_t)row*288 + 256 + rI*16 + c] = h2[c];
            }
        }
    }
    __syncthreads();

    // ---- phase D: split-k GEMM [8,288]@[288,128] + BN + ReLU ----
    {
        int half = t >> 7, outc = t & 127;
        float acc[8] = {0.f,0.f,0.f,0.f,0.f,0.f,0.f,0.f};
        int kb = half*144;
        for (int k = kb; k < kb + 144; k++) {
            float wv = __ldg(fw + (size_t)k*128 + outc);
            #pragma unroll
            for (int r = 0; r < 8; r++) acc[r] += sr[r*288 + k] * wv;
        }
        #pragma unroll
        for (int r = 0; r < 8; r++) sp[half][r][outc] = acc[r];
    }
    __syncthreads();
    if (t < 128) {
        int outc = t;
        float g = fbn[outc], be = fbn[128+outc], m = fbn[256+outc], v = fbn[384+outc];
        float sc = g * (1.0f/sqrtf(v + 1e-5f));
        #pragma unroll
        for (int r = 0; r < 8; r++) {
            float a = sp[0][r][outc] + sp[1][r][outc];
            out[(size_t)(row0 + r)*128 + outc] = fmaxf((a - m)*sc + be, 0.f);
        }
    }
}

// ---------------- launch ----------------
extern "C" void kernel_launch(void* const* d_in, const int* in_sizes, int n_in,
                              void* d_out, int out_size) {
    const float* points = (const float*)d_in[0];
    const float* rng    = (const float*)d_in[1];
    const float* sf     = (const float*)d_in[2];
    const float* sa_w0  = (const float*)d_in[3];
    const float* sa_bn0 = (const float*)d_in[4];
    const float* sa_w1  = (const float*)d_in[5];
    const float* sa_bn1 = (const float*)d_in[6];
    const float* fw     = (const float*)d_in[7];
    const float* fbn    = (const float*)d_in[8];
    float* out = (float*)d_out;

    float* fused  = out;                                          // [4096,128]
    float* feats  = out + (size_t)NROWS*128;                      // [4096,288]
    float* coords = out + (size_t)NROWS*128 + (size_t)NROWS*288;  // [4096,4]

    const int FPS_SMEM = CMPN * (int)sizeof(float4);   // 128 KB
    cudaFuncSetAttribute(fps_kernel, cudaFuncAttributeMaxDynamicSharedMemorySize, FPS_SMEM);

    fps_kernel<<<72, 256, FPS_SMEM>>>(points, rng, coords);
    backend_kernel<<<NROWS/8, 256>>>(sf, sa_w0, sa_bn0, sa_w1, sa_bn1, fw, fbn, feats, fused);
}